// round 1
// baseline (speedup 1.0000x reference)
#include <cuda_runtime.h>
#include <cstdint>

// Problem constants (fixed shapes for this problem instance)
#define NN 20000
#define EE 320000
#define FF 8
#define TT 12
#define UU 256
#define FT 96   // FF*TT

// ---------------- device scratch (no allocations allowed) ----------------
__device__ float g_deg[NN];
__device__ float g_dinv[NN];
__device__ float g_Y[NN * FT];      // aggregated features, layout [n][f*12+t]
__device__ float g_Mz[FF * UU];     // Wz @ Lzw[:U]   [f][u]
__device__ float g_Mh[FF * UU];     // Wh @ Lhw[:U]   [f][u]
__device__ float g_cz[UU];          // bz @ Lzw[:U] + Lzb
__device__ float g_ch[UU];          // bh @ Lhw[:U] + Lhb
__device__ float g_p[TT];           // softmax(attention)

// ---------------- fast math helpers ----------------
__device__ __forceinline__ float ex2f(float x) {
    float y; asm("ex2.approx.f32 %0, %1;" : "=f"(y) : "f"(x)); return y;
}
__device__ __forceinline__ float rcpf(float x) {
    float y; asm("rcp.approx.f32 %0, %1;" : "=f"(y) : "f"(x)); return y;
}
__device__ __forceinline__ float tanh_a(float x) {
    float y; asm("tanh.approx.f32 %0, %1;" : "=f"(y) : "f"(x)); return y;
}

// ---------------- phase 1: degree + normalization ----------------
__global__ void k_deg_init() {
    int i = blockIdx.x * blockDim.x + threadIdx.x;
    if (i < NN) g_deg[i] = 1.0f;   // self-loop weight 1
}

__global__ void k_deg_edges(const int* __restrict__ ei, const float* __restrict__ w) {
    int e = blockIdx.x * blockDim.x + threadIdx.x;
    if (e < EE) atomicAdd(&g_deg[ei[EE + e]], w[e]);
}

__global__ void k_dinv() {
    int i = blockIdx.x * blockDim.x + threadIdx.x;
    if (i < NN) {
        float d = g_deg[i];
        g_dinv[i] = (d > 0.0f) ? rsqrtf(d) : 0.0f;
    }
}

// Y init = self-loop contribution: dinv[n]^2 * x[n]
__global__ void k_initY(const float* __restrict__ x) {
    int i = blockIdx.x * blockDim.x + threadIdx.x;
    if (i < NN * FT) {
        int n = i / FT;
        float di = g_dinv[n];
        g_Y[i] = di * di * x[i];
    }
}

// one warp per edge: Y[dst] += norm * x[src]   (96 floats per edge)
__global__ void k_scatter(const float* __restrict__ x, const int* __restrict__ ei,
                          const float* __restrict__ w) {
    int gw = (blockIdx.x * blockDim.x + threadIdx.x) >> 5;
    if (gw >= EE) return;
    int lane = threadIdx.x & 31;
    int src = ei[gw];
    int dst = ei[EE + gw];
    float nrm = g_dinv[src] * w[gw] * g_dinv[dst];
    const float* xr = x + (size_t)src * FT;
    float* yr = g_Y + (size_t)dst * FT;
#pragma unroll
    for (int f = 0; f < 3; f++) {
        int idx = lane + f * 32;
        atomicAdd(yr + idx, nrm * __ldg(xr + idx));
    }
}

// ---------------- phase 2: fold dense weights ----------------
// grid.x = 9: blocks 0..7 compute M row f; block 8 computes c
__global__ void k_prepM(const float* __restrict__ W, const float* __restrict__ L,
                        const float* __restrict__ b, const float* __restrict__ Lb,
                        float* __restrict__ M, float* __restrict__ c) {
    __shared__ float srow[UU];
    int u = threadIdx.x;
    int f = blockIdx.x;
    if (f < FF) {
        srow[u] = W[f * UU + u];
        __syncthreads();
        float s = 0.0f;
        for (int k = 0; k < UU; k++) s = fmaf(srow[k], L[k * UU + u], s);
        M[f * UU + u] = s;
    } else {
        srow[u] = b[u];
        __syncthreads();
        float s = Lb[u];
        for (int k = 0; k < UU; k++) s = fmaf(srow[k], L[k * UU + u], s);
        c[u] = s;
    }
}

__global__ void k_softmax(const float* __restrict__ att) {
    if (threadIdx.x == 0) {
        float m = -1e30f;
        for (int t = 0; t < TT; t++) m = fmaxf(m, att[t]);
        float e[TT], s = 0.0f;
        for (int t = 0; t < TT; t++) { e[t] = __expf(att[t] - m); s += e[t]; }
        float inv = 1.0f / s;
        for (int t = 0; t < TT; t++) g_p[t] = e[t] * inv;
    }
}

// ---------------- phase 3: per-node dense + epilogue ----------------
#define NPB 8   // nodes per block (20000 / 8 = 2500 blocks)
__global__ void __launch_bounds__(UU) k_dense(const float* __restrict__ lin_w,
                                              const float* __restrict__ lin_b,
                                              float* __restrict__ out) {
    __shared__ float sY[NPB][FT];
    __shared__ float sH[NPB][UU];
    __shared__ float sp[TT];

    int u = threadIdx.x;
    int n0 = blockIdx.x * NPB;

    float mz[FF], mh[FF];
#pragma unroll
    for (int f = 0; f < FF; f++) {
        mz[f] = g_Mz[f * UU + u];
        mh[f] = g_Mh[f * UU + u];
    }
    float czu = g_cz[u];
    float chu = g_ch[u];
    if (u < TT) sp[u] = g_p[u];

    for (int i = u; i < NPB * FT; i += UU) {
        int nn = i / FT;
        int ff = i - nn * FT;
        sY[nn][ff] = g_Y[(size_t)(n0 + nn) * FT + ff];
    }
    __syncthreads();

#pragma unroll
    for (int nn = 0; nn < NPB; nn++) {
        float acc = 0.0f;
#pragma unroll
        for (int t = 0; t < TT; t++) {
            float az = czu, ah = chu;
#pragma unroll
            for (int f = 0; f < FF; f++) {
                float yv = sY[nn][f * TT + t];
                az = fmaf(yv, mz[f], az);
                ah = fmaf(yv, mh[f], ah);
            }
            // (1 - sigmoid(az)) = 1 / (1 + exp(az))
            float omz = rcpf(1.0f + ex2f(az * 1.442695041f));
            acc = fmaf(sp[t] * omz, tanh_a(ah), acc);
        }
        sH[nn][u] = fmaxf(acc, 0.0f);
    }
    __syncthreads();

    // epilogue: out[n][t] = relu(H[n]) . lin_w[:,t] + lin_b[t]
    for (int j = u; j < NPB * TT; j += UU) {
        int nn = j / TT;
        int tt = j - nn * TT;
        float s = lin_b[tt];
        int base = nn * 32;  // stagger to avoid smem bank conflicts across nn
        for (int k0 = 0; k0 < UU; k0++) {
            int k = (k0 + base) & (UU - 1);
            s = fmaf(sH[nn][k], __ldg(lin_w + k * TT + tt), s);
        }
        out[(size_t)(n0 + nn) * TT + tt] = s;
    }
}

// ---------------- launcher ----------------
extern "C" void kernel_launch(void* const* d_in, const int* in_sizes, int n_in,
                              void* d_out, int out_size) {
    const float* x      = (const float*)d_in[0];
    const int*   ei     = (const int*)d_in[1];
    const float* ew     = (const float*)d_in[2];
    const float* att    = (const float*)d_in[3];
    const float* Wz     = (const float*)d_in[4];
    const float* bz     = (const float*)d_in[5];
    // d_in[6], d_in[7] (Wr, br) unused: r-gate multiplies H0 == 0
    const float* Wh     = (const float*)d_in[8];
    const float* bh     = (const float*)d_in[9];
    const float* Lzw    = (const float*)d_in[10];
    const float* Lzb    = (const float*)d_in[11];
    // d_in[12], d_in[13] (Lrw, Lrb) unused
    const float* Lhw    = (const float*)d_in[14];
    const float* Lhb    = (const float*)d_in[15];
    const float* lin_w  = (const float*)d_in[16];
    const float* lin_b  = (const float*)d_in[17];
    float* out = (float*)d_out;

    float *dMz, *dMh, *dcz, *dch;
    cudaGetSymbolAddress((void**)&dMz, g_Mz);
    cudaGetSymbolAddress((void**)&dMh, g_Mh);
    cudaGetSymbolAddress((void**)&dcz, g_cz);
    cudaGetSymbolAddress((void**)&dch, g_ch);

    // graph normalization
    k_deg_init<<<(NN + 255) / 256, 256>>>();
    k_deg_edges<<<(EE + 255) / 256, 256>>>(ei, ew);
    k_dinv<<<(NN + 255) / 256, 256>>>();

    // aggregation: Y = D^-1/2 (A+I) D^-1/2 @ x   (all 96 feats at once)
    k_initY<<<(NN * FT + 255) / 256, 256>>>(x);
    k_scatter<<<(EE * 32 + 255) / 256, 256>>>(x, ei, ew);

    // fold weights + softmax
    k_prepM<<<FF + 1, UU>>>(Wz, Lzw, bz, Lzb, dMz, dcz);
    k_prepM<<<FF + 1, UU>>>(Wh, Lhw, bh, Lhb, dMh, dch);
    k_softmax<<<1, 32>>>(att);

    // dense pointwise + epilogue
    k_dense<<<NN / NPB, UU>>>(lin_w, lin_b, out);
}

// round 2
// speedup vs baseline: 1.0511x; 1.0511x over previous
#include <cuda_runtime.h>
#include <cstdint>

// Problem constants (fixed shapes)
#define NN 20000
#define EE 320000
#define FF 8
#define TT 12
#define UU 256
#define FT 96   // FF*TT
#define FT4 24  // FT/4

// ---------------- device scratch ----------------
__device__ float g_deg[NN];
__device__ __align__(16) float g_Y[NN * FT];   // aggregated features [n][f*12+t]
__device__ float g_Mz[FF * UU];
__device__ float g_Mh[FF * UU];
__device__ float g_cz[UU];
__device__ float g_ch[UU];
__device__ float g_p[TT];

// ---------------- fast math ----------------
__device__ __forceinline__ float ex2f(float x) {
    float y; asm("ex2.approx.f32 %0, %1;" : "=f"(y) : "f"(x)); return y;
}
__device__ __forceinline__ float rcpf(float x) {
    float y; asm("rcp.approx.f32 %0, %1;" : "=f"(y) : "f"(x)); return y;
}
__device__ __forceinline__ float tanh_a(float x) {
    float y; asm("tanh.approx.f32 %0, %1;" : "=f"(y) : "f"(x)); return y;
}
__device__ __forceinline__ void red_add_v4(float* p, float4 v) {
    asm volatile("red.global.add.v4.f32 [%0], {%1,%2,%3,%4};"
                 :: "l"(p), "f"(v.x), "f"(v.y), "f"(v.z), "f"(v.w) : "memory");
}

// ---------------- phase 1: degree ----------------
__global__ void k_deg_init() {
    int i = blockIdx.x * blockDim.x + threadIdx.x;
    if (i < NN) g_deg[i] = 1.0f;   // self-loop weight 1
}

__global__ void k_deg_edges(const int* __restrict__ ei, const float* __restrict__ w) {
    int e = blockIdx.x * blockDim.x + threadIdx.x;
    if (e < EE) atomicAdd(&g_deg[ei[EE + e]], w[e]);
}

// Y init = self-loop contribution: (1/deg[n]) * x[n], one float4 per thread
__global__ void k_initY(const float4* __restrict__ x4) {
    int i = blockIdx.x * blockDim.x + threadIdx.x;
    if (i < NN * FT4) {
        int n = i / FT4;
        float s = 1.0f / g_deg[n];   // dinv^2
        float4 v = __ldg(x4 + i);
        v.x *= s; v.y *= s; v.z *= s; v.w *= s;
        reinterpret_cast<float4*>(g_Y)[i] = v;
    }
}

// warp per edge: lanes 0..23 each handle one float4 via red.v4
__global__ void k_scatter(const float4* __restrict__ x4, const int* __restrict__ ei,
                          const float* __restrict__ w) {
    int gw = (blockIdx.x * blockDim.x + threadIdx.x) >> 5;
    if (gw >= EE) return;
    int lane = threadIdx.x & 31;
    int src = __ldg(ei + gw);
    int dst = __ldg(ei + EE + gw);
    float nrm = rsqrtf(g_deg[src]) * __ldg(w + gw) * rsqrtf(g_deg[dst]);
    if (lane < FT4) {
        float4 v = __ldg(x4 + (size_t)src * FT4 + lane);
        v.x *= nrm; v.y *= nrm; v.z *= nrm; v.w *= nrm;
        red_add_v4(&g_Y[(size_t)dst * FT + lane * 4], v);
    }
}

// ---------------- phase 2: fold dense weights + softmax (single launch) ----------------
// blocks 0..8: z-path (8 rows of M + bias), blocks 9..17: h-path, block 18: softmax
__global__ void k_prep(const float* __restrict__ Wz, const float* __restrict__ Lzw,
                       const float* __restrict__ bz, const float* __restrict__ Lzb,
                       const float* __restrict__ Wh, const float* __restrict__ Lhw,
                       const float* __restrict__ bh, const float* __restrict__ Lhb,
                       const float* __restrict__ att) {
    int blk = blockIdx.x;
    int u = threadIdx.x;
    if (blk == 18) {
        if (u == 0) {
            float m = -1e30f;
            for (int t = 0; t < TT; t++) m = fmaxf(m, att[t]);
            float e[TT], s = 0.0f;
            for (int t = 0; t < TT; t++) { e[t] = __expf(att[t] - m); s += e[t]; }
            float inv = 1.0f / s;
            for (int t = 0; t < TT; t++) g_p[t] = e[t] * inv;
        }
        return;
    }
    bool isz = blk < 9;
    int f = isz ? blk : blk - 9;
    const float* W = isz ? Wz : Wh;
    const float* L = isz ? Lzw : Lhw;
    const float* b = isz ? bz : bh;
    const float* Lb = isz ? Lzb : Lhb;
    float* M = isz ? g_Mz : g_Mh;
    float* c = isz ? g_cz : g_ch;

    __shared__ float srow[UU];
    if (f < FF) {
        srow[u] = W[f * UU + u];
        __syncthreads();
        float s = 0.0f;
        for (int k = 0; k < UU; k++) s = fmaf(srow[k], L[k * UU + u], s);
        M[f * UU + u] = s;
    } else {
        srow[u] = b[u];
        __syncthreads();
        float s = Lb[u];
        for (int k = 0; k < UU; k++) s = fmaf(srow[k], L[k * UU + u], s);
        c[u] = s;
    }
}

// ---------------- phase 3: per-node dense + epilogue ----------------
#define NPB 8   // nodes per block
__global__ void __launch_bounds__(UU) k_dense(const float* __restrict__ lin_w,
                                              const float* __restrict__ lin_b,
                                              float* __restrict__ out) {
    __shared__ float sY[NPB][FT];
    __shared__ float sH[NPB][UU];
    __shared__ float sp[TT];

    int u = threadIdx.x;
    int n0 = blockIdx.x * NPB;

    float mz[FF], mh[FF];
#pragma unroll
    for (int f = 0; f < FF; f++) {
        mz[f] = g_Mz[f * UU + u];
        mh[f] = g_Mh[f * UU + u];
    }
    float czu = g_cz[u];
    float chu = g_ch[u];
    if (u < TT) sp[u] = g_p[u];

    for (int i = u; i < NPB * FT4; i += UU) {
        int nn = i / FT4;
        int ff = i - nn * FT4;
        reinterpret_cast<float4*>(sY[nn])[ff] =
            reinterpret_cast<const float4*>(g_Y)[(size_t)(n0 + nn) * FT4 + ff];
    }
    __syncthreads();

#pragma unroll
    for (int nn = 0; nn < NPB; nn++) {
        float acc = 0.0f;
#pragma unroll
        for (int t = 0; t < TT; t++) {
            float az = czu, ah = chu;
#pragma unroll
            for (int f = 0; f < FF; f++) {
                float yv = sY[nn][f * TT + t];
                az = fmaf(yv, mz[f], az);
                ah = fmaf(yv, mh[f], ah);
            }
            // (1 - sigmoid(az)) = 1/(1+exp(az))
            float omz = rcpf(1.0f + ex2f(az * 1.442695041f));
            acc = fmaf(sp[t] * omz, tanh_a(ah), acc);
        }
        sH[nn][u] = fmaxf(acc, 0.0f);
    }
    __syncthreads();

    // epilogue: out[n][t] = relu(H[n]) . lin_w[:,t] + lin_b[t]
    for (int j = u; j < NPB * TT; j += UU) {
        int nn = j / TT;
        int tt = j - nn * TT;
        float s = lin_b[tt];
        int base = nn * 32;  // stagger to dodge smem bank conflicts
        for (int k0 = 0; k0 < UU; k0++) {
            int k = (k0 + base) & (UU - 1);
            s = fmaf(sH[nn][k], __ldg(lin_w + k * TT + tt), s);
        }
        out[(size_t)(n0 + nn) * TT + tt] = s;
    }
}

// ---------------- launcher ----------------
extern "C" void kernel_launch(void* const* d_in, const int* in_sizes, int n_in,
                              void* d_out, int out_size) {
    const float* x      = (const float*)d_in[0];
    const int*   ei     = (const int*)d_in[1];
    const float* ew     = (const float*)d_in[2];
    const float* att    = (const float*)d_in[3];
    const float* Wz     = (const float*)d_in[4];
    const float* bz     = (const float*)d_in[5];
    // d_in[6..7] (Wr, br) dead: r-gate multiplies H0 == 0
    const float* Wh     = (const float*)d_in[8];
    const float* bh     = (const float*)d_in[9];
    const float* Lzw    = (const float*)d_in[10];
    const float* Lzb    = (const float*)d_in[11];
    // d_in[12..13] (Lrw, Lrb) dead
    const float* Lhw    = (const float*)d_in[14];
    const float* Lhb    = (const float*)d_in[15];
    const float* lin_w  = (const float*)d_in[16];
    const float* lin_b  = (const float*)d_in[17];
    float* out = (float*)d_out;

    const float4* x4 = (const float4*)x;

    k_deg_init<<<(NN + 255) / 256, 256>>>();
    k_deg_edges<<<(EE + 255) / 256, 256>>>(ei, ew);
    k_initY<<<(NN * FT4 + 255) / 256, 256>>>(x4);
    k_scatter<<<(EE * 32 + 255) / 256, 256>>>(x4, ei, ew);
    k_prep<<<19, UU>>>(Wz, Lzw, bz, Lzb, Wh, Lhw, bh, Lhb, att);
    k_dense<<<NN / NPB, UU>>>(lin_w, lin_b, out);
}

// round 3
// speedup vs baseline: 1.1741x; 1.1171x over previous
#include <cuda_runtime.h>
#include <cstdint>

#define NN 20000
#define EE 320000
#define FF 8
#define TT 12
#define UU 256
#define FT 96   // FF*TT
#define FT4 24  // FT/4

// ---------------- device scratch ----------------
__device__ float g_deg[NN];
__device__ int   g_cnt[NN];
__device__ int   g_off[NN + 1];
__device__ int   g_cur[NN];
__device__ int   g_esrc[EE];
__device__ float g_enrm[EE];
__device__ __align__(16) float g_Y[NN * FT];
__device__ float g_Mz[FF * UU];
__device__ float g_Mh[FF * UU];
__device__ float g_cz[UU];
__device__ float g_ch[UU];
__device__ float g_p[TT];

// ---------------- fast math ----------------
__device__ __forceinline__ float tanh_a(float x) {
    float y; asm("tanh.approx.f32 %0, %1;" : "=f"(y) : "f"(x)); return y;
}
__device__ __forceinline__ unsigned long long fma2(unsigned long long a,
                                                   unsigned long long b,
                                                   unsigned long long c) {
    unsigned long long d;
    asm("fma.rn.f32x2 %0, %1, %2, %3;" : "=l"(d) : "l"(a), "l"(b), "l"(c));
    return d;
}
__device__ __forceinline__ unsigned long long pack2(float lo, float hi) {
    unsigned long long r;
    asm("mov.b64 %0, {%1,%2};" : "=l"(r) : "f"(lo), "f"(hi));
    return r;
}
__device__ __forceinline__ void unpack2(unsigned long long v, float& lo, float& hi) {
    asm("mov.b64 {%0,%1}, %2;" : "=f"(lo), "=f"(hi) : "l"(v));
}

// ---------------- phase 1: degree + counts ----------------
__global__ void k_init() {
    int i = blockIdx.x * blockDim.x + threadIdx.x;
    if (i < NN) { g_deg[i] = 1.0f; g_cnt[i] = 0; }
}

__global__ void k_edges(const int* __restrict__ ei, const float* __restrict__ w) {
    int e = blockIdx.x * blockDim.x + threadIdx.x;
    if (e < EE) {
        int dst = __ldg(ei + EE + e);
        atomicAdd(&g_deg[dst], __ldg(w + e));
        atomicAdd(&g_cnt[dst], 1);
    }
}

// single-block exclusive prefix scan over g_cnt -> g_off / g_cur
__global__ void __launch_bounds__(1024) k_scan() {
    __shared__ int wsum[32];
    __shared__ int carry_s;
    int tid = threadIdx.x, lane = tid & 31, wid = tid >> 5;
    if (tid == 0) carry_s = 0;
    __syncthreads();
    const int CHUNKS = (NN + 1023) / 1024;
    for (int c = 0; c < CHUNKS; c++) {
        int i = c * 1024 + tid;
        int v = (i < NN) ? g_cnt[i] : 0;
        int s = v;
#pragma unroll
        for (int d = 1; d < 32; d <<= 1) {
            int t = __shfl_up_sync(0xffffffffu, s, d);
            if (lane >= d) s += t;
        }
        if (lane == 31) wsum[wid] = s;
        __syncthreads();
        if (wid == 0) {
            int ws = wsum[lane];
#pragma unroll
            for (int d = 1; d < 32; d <<= 1) {
                int t = __shfl_up_sync(0xffffffffu, ws, d);
                if (lane >= d) ws += t;
            }
            wsum[lane] = ws;
        }
        __syncthreads();
        int warp_excl = (wid == 0) ? 0 : wsum[wid - 1];
        int excl = s - v + warp_excl + carry_s;
        if (i < NN) { g_off[i] = excl; g_cur[i] = excl; }
        int total = wsum[31];
        __syncthreads();
        if (tid == 0) carry_s += total;
        __syncthreads();
    }
    if (tid == 0) g_off[NN] = carry_s;
}

// fill per-dst edge lists: (src, precomputed norm)
__global__ void k_fill(const int* __restrict__ ei, const float* __restrict__ w) {
    int e = blockIdx.x * blockDim.x + threadIdx.x;
    if (e < EE) {
        int src = __ldg(ei + e);
        int dst = __ldg(ei + EE + e);
        int p = atomicAdd(&g_cur[dst], 1);
        g_esrc[p] = src;
        g_enrm[p] = rsqrtf(g_deg[src]) * __ldg(w + e) * rsqrtf(g_deg[dst]);
    }
}

// warp-per-node gather: Y[n] = dinv[n]^2 * x[n] + sum_e nrm_e * x[src_e]
__global__ void k_gather(const float4* __restrict__ x4) {
    int node = (blockIdx.x * blockDim.x + threadIdx.x) >> 5;
    if (node >= NN) return;
    int lane = threadIdx.x & 31;
    int beg = g_off[node], end = g_off[node + 1];

    float4 acc = make_float4(0.f, 0.f, 0.f, 0.f);
    if (lane < FT4) {
        float s = 1.0f / g_deg[node];   // dinv^2, self-loop weight 1
        float4 v = __ldg(x4 + (size_t)node * FT4 + lane);
        acc.x = s * v.x; acc.y = s * v.y; acc.z = s * v.z; acc.w = s * v.w;
    }
    for (int i = beg; i < end; i++) {
        int   src = __ldg(&g_esrc[i]);   // broadcast loads (same addr all lanes)
        float nrm = __ldg(&g_enrm[i]);
        if (lane < FT4) {
            float4 v = __ldg(x4 + (size_t)src * FT4 + lane);
            acc.x = fmaf(nrm, v.x, acc.x);
            acc.y = fmaf(nrm, v.y, acc.y);
            acc.z = fmaf(nrm, v.z, acc.z);
            acc.w = fmaf(nrm, v.w, acc.w);
        }
    }
    if (lane < FT4)
        reinterpret_cast<float4*>(g_Y)[(size_t)node * FT4 + lane] = acc;
}

// ---------------- phase 2: fold weights + softmax (one launch) ----------------
__global__ void k_prep(const float* __restrict__ Wz, const float* __restrict__ Lzw,
                       const float* __restrict__ bz, const float* __restrict__ Lzb,
                       const float* __restrict__ Wh, const float* __restrict__ Lhw,
                       const float* __restrict__ bh, const float* __restrict__ Lhb,
                       const float* __restrict__ att) {
    int blk = blockIdx.x;
    int u = threadIdx.x;
    if (blk == 18) {
        if (u == 0) {
            float m = -1e30f;
            for (int t = 0; t < TT; t++) m = fmaxf(m, att[t]);
            float e[TT], s = 0.0f;
            for (int t = 0; t < TT; t++) { e[t] = __expf(att[t] - m); s += e[t]; }
            float inv = 1.0f / s;
            for (int t = 0; t < TT; t++) g_p[t] = e[t] * inv;
        }
        return;
    }
    bool isz = blk < 9;
    int f = isz ? blk : blk - 9;
    const float* W = isz ? Wz : Wh;
    const float* L = isz ? Lzw : Lhw;
    const float* b = isz ? bz : bh;
    const float* Lb = isz ? Lzb : Lhb;
    float* M = isz ? g_Mz : g_Mh;
    float* c = isz ? g_cz : g_ch;

    __shared__ float srow[UU];
    if (f < FF) {
        srow[u] = W[f * UU + u];
        __syncthreads();
        float s = 0.0f;
        for (int k = 0; k < UU; k++) s = fmaf(srow[k], L[k * UU + u], s);
        M[f * UU + u] = s;
    } else {
        srow[u] = b[u];
        __syncthreads();
        float s = Lb[u];
        for (int k = 0; k < UU; k++) s = fmaf(srow[k], L[k * UU + u], s);
        c[u] = s;
    }
}

// ---------------- phase 3: per-node dense + epilogue ----------------
#define NPB 8
__global__ void __launch_bounds__(UU) k_dense(const float* __restrict__ lin_w,
                                              const float* __restrict__ lin_b,
                                              float* __restrict__ out) {
    __shared__ __align__(16) float sY[NPB][FT];
    __shared__ float sH[NPB][UU];
    __shared__ float sp[TT];

    int u = threadIdx.x;
    int n0 = blockIdx.x * NPB;

    unsigned long long mz2[FF], mh2[FF];
#pragma unroll
    for (int f = 0; f < FF; f++) {
        float mz = g_Mz[f * UU + u];
        float mh = g_Mh[f * UU + u];
        mz2[f] = pack2(mz, mz);
        mh2[f] = pack2(mh, mh);
    }
    unsigned long long cz2, ch2;
    { float cz = g_cz[u], ch = g_ch[u]; cz2 = pack2(cz, cz); ch2 = pack2(ch, ch); }
    if (u < TT) sp[u] = g_p[u];

    for (int i = u; i < NPB * FT4; i += UU) {
        int nn = i / FT4;
        int ff = i - nn * FT4;
        reinterpret_cast<float4*>(sY[nn])[ff] =
            reinterpret_cast<const float4*>(g_Y)[(size_t)(n0 + nn) * FT4 + ff];
    }
    __syncthreads();

#pragma unroll
    for (int nn = 0; nn < NPB; nn++) {
        const unsigned long long* yrow = reinterpret_cast<const unsigned long long*>(sY[nn]);
        float acc = 0.0f;
#pragma unroll
        for (int tp = 0; tp < TT / 2; tp++) {
            unsigned long long az = cz2, ah = ch2;
#pragma unroll
            for (int f = 0; f < FF; f++) {
                unsigned long long y2 = yrow[f * (TT / 2) + tp];  // (t=2tp, 2tp+1)
                az = fma2(y2, mz2[f], az);
                ah = fma2(y2, mh2[f], ah);
            }
            float a0, a1, h0, h1;
            unpack2(az, a0, a1);
            unpack2(ah, h0, h1);
            // 1 - sigmoid(a) = 0.5 - 0.5*tanh(a/2)
            float o0 = fmaf(-0.5f, tanh_a(0.5f * a0), 0.5f);
            float o1 = fmaf(-0.5f, tanh_a(0.5f * a1), 0.5f);
            acc = fmaf(sp[2 * tp] * o0, tanh_a(h0), acc);
            acc = fmaf(sp[2 * tp + 1] * o1, tanh_a(h1), acc);
        }
        sH[nn][u] = fmaxf(acc, 0.0f);
    }
    __syncthreads();

    for (int j = u; j < NPB * TT; j += UU) {
        int nn = j / TT;
        int tt = j - nn * TT;
        float s = lin_b[tt];
        int base = nn * 32;
        for (int k0 = 0; k0 < UU; k0++) {
            int k = (k0 + base) & (UU - 1);
            s = fmaf(sH[nn][k], __ldg(lin_w + k * TT + tt), s);
        }
        out[(size_t)(n0 + nn) * TT + tt] = s;
    }
}

// ---------------- launcher ----------------
extern "C" void kernel_launch(void* const* d_in, const int* in_sizes, int n_in,
                              void* d_out, int out_size) {
    const float* x      = (const float*)d_in[0];
    const int*   ei     = (const int*)d_in[1];
    const float* ew     = (const float*)d_in[2];
    const float* att    = (const float*)d_in[3];
    const float* Wz     = (const float*)d_in[4];
    const float* bz     = (const float*)d_in[5];
    // d_in[6..7] (Wr, br) dead: r-gate multiplies H0 == 0
    const float* Wh     = (const float*)d_in[8];
    const float* bh     = (const float*)d_in[9];
    const float* Lzw    = (const float*)d_in[10];
    const float* Lzb    = (const float*)d_in[11];
    // d_in[12..13] (Lrw, Lrb) dead
    const float* Lhw    = (const float*)d_in[14];
    const float* Lhb    = (const float*)d_in[15];
    const float* lin_w  = (const float*)d_in[16];
    const float* lin_b  = (const float*)d_in[17];
    float* out = (float*)d_out;

    const float4* x4 = (const float4*)x;

    k_init<<<(NN + 255) / 256, 256>>>();
    k_edges<<<(EE + 255) / 256, 256>>>(ei, ew);
    k_scan<<<1, 1024>>>();
    k_fill<<<(EE + 255) / 256, 256>>>(ei, ew);
    k_prep<<<19, UU>>>(Wz, Lzw, bz, Lzb, Wh, Lhw, bh, Lhb, att);
    k_gather<<<(NN * 32 + 255) / 256, 256>>>(x4);
    k_dense<<<NN / NPB, UU>>>(lin_w, lin_b, out);
}

// round 4
// speedup vs baseline: 1.5881x; 1.3525x over previous
#include <cuda_runtime.h>
#include <cstdint>

#define NN 20000
#define EE 320000
#define FF 8
#define TT 12
#define UU 256
#define FT 96   // FF*TT
#define FT4 24  // FT/4

// ---------------- device scratch ----------------
// g_dc: [0,NN) = deg-minus-selfloop (float bits), [NN,2NN) = cnt (int). Zero-init by memset.
__device__ unsigned g_dc[2 * NN];
__device__ int   g_off[NN + 1];
__device__ int   g_cur[NN];
__device__ uint2 g_edge[EE];        // (src, norm-bits) per dst-sorted slot
__device__ float g_Mz[FF * UU];     // prescaled by 0.5
__device__ float g_Mh[FF * UU];
__device__ float g_cz[UU];          // prescaled by 0.5
__device__ float g_ch[UU];
__device__ float g_p[TT];           // 0.5 * softmax(attention)

// ---------------- fast math ----------------
__device__ __forceinline__ float tanh_a(float x) {
    float y; asm("tanh.approx.f32 %0, %1;" : "=f"(y) : "f"(x)); return y;
}
__device__ __forceinline__ unsigned long long fma2(unsigned long long a,
                                                   unsigned long long b,
                                                   unsigned long long c) {
    unsigned long long d;
    asm("fma.rn.f32x2 %0, %1, %2, %3;" : "=l"(d) : "l"(a), "l"(b), "l"(c));
    return d;
}
__device__ __forceinline__ unsigned long long pack2(float lo, float hi) {
    unsigned long long r;
    asm("mov.b64 %0, {%1,%2};" : "=l"(r) : "f"(lo), "f"(hi));
    return r;
}
__device__ __forceinline__ void unpack2(unsigned long long v, float& lo, float& hi) {
    asm("mov.b64 {%0,%1}, %2;" : "=f"(lo), "=f"(hi) : "l"(v));
}

// ---------------- phase 1: per-dst degree + edge counts ----------------
__global__ void k_edges(const int* __restrict__ ei, const float* __restrict__ w) {
    int e = blockIdx.x * blockDim.x + threadIdx.x;
    if (e < EE) {
        int dst = __ldg(ei + EE + e);
        atomicAdd(reinterpret_cast<float*>(&g_dc[dst]), __ldg(w + e));
        atomicAdd(reinterpret_cast<int*>(&g_dc[NN + dst]), 1);
    }
}

// ---------------- phase 2: scan (block 0) + weight-fold (blocks 1..18) + softmax (block 19) ----
__global__ void __launch_bounds__(1024) k_scanprep(
        const float* __restrict__ Wz, const float* __restrict__ Lzw,
        const float* __restrict__ bz, const float* __restrict__ Lzb,
        const float* __restrict__ Wh, const float* __restrict__ Lhw,
        const float* __restrict__ bh, const float* __restrict__ Lhb,
        const float* __restrict__ att) {
    int blk = blockIdx.x;
    int tid = threadIdx.x;

    if (blk == 0) {
        // single-block exclusive scan over cnt -> g_off / g_cur
        __shared__ int wsum[32];
        __shared__ int carry_s;
        int lane = tid & 31, wid = tid >> 5;
        if (tid == 0) carry_s = 0;
        __syncthreads();
        const int CHUNKS = (NN + 1023) / 1024;
        for (int c = 0; c < CHUNKS; c++) {
            int i = c * 1024 + tid;
            int v = (i < NN) ? (int)g_dc[NN + i] : 0;
            int s = v;
#pragma unroll
            for (int d = 1; d < 32; d <<= 1) {
                int t = __shfl_up_sync(0xffffffffu, s, d);
                if (lane >= d) s += t;
            }
            if (lane == 31) wsum[wid] = s;
            __syncthreads();
            if (wid == 0) {
                int ws = wsum[lane];
#pragma unroll
                for (int d = 1; d < 32; d <<= 1) {
                    int t = __shfl_up_sync(0xffffffffu, ws, d);
                    if (lane >= d) ws += t;
                }
                wsum[lane] = ws;
            }
            __syncthreads();
            int warp_excl = (wid == 0) ? 0 : wsum[wid - 1];
            int excl = s - v + warp_excl + carry_s;
            if (i < NN) { g_off[i] = excl; g_cur[i] = excl; }
            int total = wsum[31];
            __syncthreads();
            if (tid == 0) carry_s += total;
            __syncthreads();
        }
        if (tid == 0) g_off[NN] = carry_s;
        return;
    }

    if (blk == 19) {
        if (tid == 0) {
            float m = -1e30f;
            for (int t = 0; t < TT; t++) m = fmaxf(m, att[t]);
            float e[TT], s = 0.0f;
            for (int t = 0; t < TT; t++) { e[t] = __expf(att[t] - m); s += e[t]; }
            float inv = 0.5f / s;                      // fold the 1/2 here
            for (int t = 0; t < TT; t++) g_p[t] = e[t] * inv;
        }
        return;
    }

    // weight folding: blocks 1..9 -> z path, 10..18 -> h path
    if (tid >= UU) return;
    int u = tid;
    bool isz = blk <= 9;
    int f = isz ? blk - 1 : blk - 10;
    const float* W  = isz ? Wz : Wh;
    const float* L  = isz ? Lzw : Lhw;
    const float* b  = isz ? bz : bh;
    const float* Lb = isz ? Lzb : Lhb;
    float* M = isz ? g_Mz : g_Mh;
    float* c = isz ? g_cz : g_ch;
    float scale = isz ? 0.5f : 1.0f;                   // tanh(az/2) prescale

    __shared__ float srow[UU];
    if (f < FF) {
        srow[u] = W[f * UU + u];
        __syncthreads();
        float s = 0.0f;
        for (int k = 0; k < UU; k++) s = fmaf(srow[k], L[k * UU + u], s);
        M[f * UU + u] = scale * s;
    } else {
        srow[u] = b[u];
        __syncthreads();
        float s = Lb[u];
        for (int k = 0; k < UU; k++) s = fmaf(srow[k], L[k * UU + u], s);
        c[u] = scale * s;
    }
}

// ---------------- phase 3: fill per-dst edge slots ----------------
__global__ void k_fill(const int* __restrict__ ei, const float* __restrict__ w) {
    int e = blockIdx.x * blockDim.x + threadIdx.x;
    if (e < EE) {
        int src = __ldg(ei + e);
        int dst = __ldg(ei + EE + e);
        float ds = __uint_as_float(g_dc[src]) + 1.0f;   // +1 self-loop
        float dd = __uint_as_float(g_dc[dst]) + 1.0f;
        float nrm = rsqrtf(ds) * __ldg(w + e) * rsqrtf(dd);
        int p = atomicAdd(&g_cur[dst], 1);
        g_edge[p] = make_uint2((unsigned)src, __float_as_uint(nrm));
    }
}

// ---------------- phase 4: fused gather + gates + epilogue ----------------
#define NPB 8
__global__ void __launch_bounds__(UU) k_dense(const float4* __restrict__ x4,
                                              const float* __restrict__ lin_w,
                                              const float* __restrict__ lin_b,
                                              float* __restrict__ out) {
    __shared__ __align__(16) float sY[NPB][FT];
    __shared__ float sH[NPB][UU];
    __shared__ float sp[TT];

    int u = threadIdx.x;
    int lane = u & 31;
    int wid = u >> 5;
    int n0 = blockIdx.x * NPB;

    // ---- gather: warp w aggregates node n0+w directly into sY[w] ----
    {
        int node = n0 + wid;
        int beg = g_off[node], end = g_off[node + 1];
        float4 acc = make_float4(0.f, 0.f, 0.f, 0.f);
        if (lane < FT4) {
            float s = 1.0f / (__uint_as_float(g_dc[node]) + 1.0f);   // dinv^2
            float4 v = __ldg(x4 + (size_t)node * FT4 + lane);
            acc.x = s * v.x; acc.y = s * v.y; acc.z = s * v.z; acc.w = s * v.w;
        }
        for (int i = beg; i < end; i++) {
            uint2 e = __ldg(&g_edge[i]);           // broadcast
            float nrm = __uint_as_float(e.y);
            if (lane < FT4) {
                float4 v = __ldg(x4 + (size_t)e.x * FT4 + lane);
                acc.x = fmaf(nrm, v.x, acc.x);
                acc.y = fmaf(nrm, v.y, acc.y);
                acc.z = fmaf(nrm, v.z, acc.z);
                acc.w = fmaf(nrm, v.w, acc.w);
            }
        }
        if (lane < FT4)
            reinterpret_cast<float4*>(sY[wid])[lane] = acc;
    }
    if (u < TT) sp[u] = g_p[u];                    // already 0.5*p
    __syncthreads();

    // ---- gates: thread u, loop nodes ----
    unsigned long long mz2[FF], mh2[FF];
#pragma unroll
    for (int f = 0; f < FF; f++) {
        float mz = g_Mz[f * UU + u];
        float mh = g_Mh[f * UU + u];
        mz2[f] = pack2(mz, mz);
        mh2[f] = pack2(mh, mh);
    }
    unsigned long long cz2, ch2;
    { float cz = g_cz[u], ch = g_ch[u]; cz2 = pack2(cz, cz); ch2 = pack2(ch, ch); }

#pragma unroll
    for (int nn = 0; nn < NPB; nn++) {
        const unsigned long long* yrow = reinterpret_cast<const unsigned long long*>(sY[nn]);
        float acc = 0.0f;
#pragma unroll
        for (int tp = 0; tp < TT / 2; tp++) {
            unsigned long long az = cz2, ah = ch2;
#pragma unroll
            for (int f = 0; f < FF; f++) {
                unsigned long long y2 = yrow[f * (TT / 2) + tp];
                az = fma2(y2, mz2[f], az);          // az holds a/2 (prescaled)
                ah = fma2(y2, mh2[f], ah);
            }
            float a0, a1, h0, h1;
            unpack2(az, a0, a1);
            unpack2(ah, h0, h1);
            float tz0 = tanh_a(a0), tz1 = tanh_a(a1);
            float q0 = sp[2 * tp], q1 = sp[2 * tp + 1];
            float r0 = fmaf(-tz0, q0, q0);          // q*(1-tanh(a/2)) = p*(1-sigmoid)
            float r1 = fmaf(-tz1, q1, q1);
            acc = fmaf(r0, tanh_a(h0), acc);
            acc = fmaf(r1, tanh_a(h1), acc);
        }
        sH[nn][u] = fmaxf(acc, 0.0f);
    }
    __syncthreads();

    // ---- epilogue: warp w -> node n0+w; out[n,t] = relu(H) . lin_w[:,t] + b ----
    {
        float part[TT];
#pragma unroll
        for (int t = 0; t < TT; t++) part[t] = 0.0f;
#pragma unroll
        for (int q = 0; q < 8; q++) {
            int k = lane + 32 * q;                  // conflict-free (lane-major)
            float h = sH[wid][k];
            const float4* wr = reinterpret_cast<const float4*>(lin_w + k * TT);
            float4 w0 = __ldg(wr + 0);
            float4 w1 = __ldg(wr + 1);
            float4 w2 = __ldg(wr + 2);
            part[0] = fmaf(h, w0.x, part[0]);  part[1]  = fmaf(h, w0.y, part[1]);
            part[2] = fmaf(h, w0.z, part[2]);  part[3]  = fmaf(h, w0.w, part[3]);
            part[4] = fmaf(h, w1.x, part[4]);  part[5]  = fmaf(h, w1.y, part[5]);
            part[6] = fmaf(h, w1.z, part[6]);  part[7]  = fmaf(h, w1.w, part[7]);
            part[8] = fmaf(h, w2.x, part[8]);  part[9]  = fmaf(h, w2.y, part[9]);
            part[10] = fmaf(h, w2.z, part[10]); part[11] = fmaf(h, w2.w, part[11]);
        }
#pragma unroll
        for (int d = 16; d > 0; d >>= 1)
#pragma unroll
            for (int t = 0; t < TT; t++)
                part[t] += __shfl_xor_sync(0xffffffffu, part[t], d);
        if (lane < TT)
            out[(size_t)(n0 + wid) * TT + lane] = part[lane] + __ldg(lin_b + lane);
    }
}

// ---------------- launcher ----------------
extern "C" void kernel_launch(void* const* d_in, const int* in_sizes, int n_in,
                              void* d_out, int out_size) {
    const float* x      = (const float*)d_in[0];
    const int*   ei     = (const int*)d_in[1];
    const float* ew     = (const float*)d_in[2];
    const float* att    = (const float*)d_in[3];
    const float* Wz     = (const float*)d_in[4];
    const float* bz     = (const float*)d_in[5];
    // d_in[6..7] (Wr, br) dead: r-gate multiplies H0 == 0
    const float* Wh     = (const float*)d_in[8];
    const float* bh     = (const float*)d_in[9];
    const float* Lzw    = (const float*)d_in[10];
    const float* Lzb    = (const float*)d_in[11];
    // d_in[12..13] (Lrw, Lrb) dead
    const float* Lhw    = (const float*)d_in[14];
    const float* Lhb    = (const float*)d_in[15];
    const float* lin_w  = (const float*)d_in[16];
    const float* lin_b  = (const float*)d_in[17];
    float* out = (float*)d_out;

    void* dc_ptr = nullptr;
    cudaGetSymbolAddress(&dc_ptr, g_dc);

    cudaMemsetAsync(dc_ptr, 0, 2 * NN * sizeof(unsigned));
    k_edges<<<(EE + 255) / 256, 256>>>(ei, ew);
    k_scanprep<<<20, 1024>>>(Wz, Lzw, bz, Lzb, Wh, Lhw, bh, Lhb, att);
    k_fill<<<(EE + 255) / 256, 256>>>(ei, ew);
    k_dense<<<NN / NPB, UU>>>((const float4*)x, lin_w, lin_b, out);
}

// round 5
// speedup vs baseline: 1.6862x; 1.0618x over previous
#include <cuda_runtime.h>
#include <cstdint>

#define NN 20000
#define EE 320000
#define FF 8
#define TT 12
#define UU 256
#define FT 96   // FF*TT
#define FT4 24  // FT/4
#define EQ (EE / 4)   // edges per thread-quarter

// ---------------- device scratch ----------------
// g_dc: [0,NN) = deg-minus-selfloop (float bits), [NN,2NN) = cnt (int). Zero-init by memset.
__device__ unsigned g_dc[2 * NN];
__device__ int   g_off[NN + 1];
__device__ int   g_cur[NN];
__device__ uint2 g_edge[EE];        // (src, norm-bits) per dst-sorted slot
__device__ float g_Mz[FF * UU];     // prescaled by 0.5
__device__ float g_Mh[FF * UU];
__device__ float g_cz[UU];          // prescaled by 0.5
__device__ float g_ch[UU];
__device__ float g_p[TT];           // 0.5 * softmax(attention)

// ---------------- fast math ----------------
__device__ __forceinline__ float tanh_a(float x) {
    float y; asm("tanh.approx.f32 %0, %1;" : "=f"(y) : "f"(x)); return y;
}
__device__ __forceinline__ unsigned long long fma2(unsigned long long a,
                                                   unsigned long long b,
                                                   unsigned long long c) {
    unsigned long long d;
    asm("fma.rn.f32x2 %0, %1, %2, %3;" : "=l"(d) : "l"(a), "l"(b), "l"(c));
    return d;
}
__device__ __forceinline__ unsigned long long pack2(float lo, float hi) {
    unsigned long long r;
    asm("mov.b64 %0, {%1,%2};" : "=l"(r) : "f"(lo), "f"(hi));
    return r;
}
__device__ __forceinline__ void unpack2(unsigned long long v, float& lo, float& hi) {
    asm("mov.b64 {%0,%1}, %2;" : "=f"(lo), "=f"(hi) : "l"(v));
}
__device__ __forceinline__ float4 fma4s(float s, float4 v, float4 a) {
    a.x = fmaf(s, v.x, a.x); a.y = fmaf(s, v.y, a.y);
    a.z = fmaf(s, v.z, a.z); a.w = fmaf(s, v.w, a.w);
    return a;
}

// ---------------- phase 1: per-dst degree + edge counts (4 edges/thread) ----------------
__global__ void k_edges(const int* __restrict__ ei, const float* __restrict__ w) {
    int t = blockIdx.x * blockDim.x + threadIdx.x;
    if (t >= EQ) return;
    int   dst[4];
    float wv[4];
#pragma unroll
    for (int j = 0; j < 4; j++) {
        int e = t + j * EQ;
        dst[j] = __ldg(ei + EE + e);
        wv[j]  = __ldg(w + e);
    }
#pragma unroll
    for (int j = 0; j < 4; j++) {
        atomicAdd(reinterpret_cast<float*>(&g_dc[dst[j]]), wv[j]);
        atomicAdd(reinterpret_cast<int*>(&g_dc[NN + dst[j]]), 1);
    }
}

// ---------------- phase 2: scan (blk 0) + weight-fold (1..18) + softmax (19) ----------------
#define CHUNKS ((NN + 1023) / 1024)
__global__ void __launch_bounds__(1024) k_scanprep(
        const float* __restrict__ Wz, const float* __restrict__ Lzw,
        const float* __restrict__ bz, const float* __restrict__ Lzb,
        const float* __restrict__ Wh, const float* __restrict__ Lhw,
        const float* __restrict__ bh, const float* __restrict__ Lhb,
        const float* __restrict__ att) {
    int blk = blockIdx.x;
    int tid = threadIdx.x;

    if (blk == 0) {
        __shared__ int wsum[32];
        __shared__ int carry_s;
        int lane = tid & 31, wid = tid >> 5;
        int vv[CHUNKS];
#pragma unroll
        for (int c = 0; c < CHUNKS; c++) {           // front-batch all loads (MLP=20)
            int i = c * 1024 + tid;
            vv[c] = (i < NN) ? (int)g_dc[NN + i] : 0;
        }
        if (tid == 0) carry_s = 0;
        __syncthreads();
#pragma unroll
        for (int c = 0; c < CHUNKS; c++) {
            int i = c * 1024 + tid;
            int v = vv[c];
            int s = v;
#pragma unroll
            for (int d = 1; d < 32; d <<= 1) {
                int t2 = __shfl_up_sync(0xffffffffu, s, d);
                if (lane >= d) s += t2;
            }
            if (lane == 31) wsum[wid] = s;
            __syncthreads();
            if (wid == 0) {
                int ws = wsum[lane];
#pragma unroll
                for (int d = 1; d < 32; d <<= 1) {
                    int t2 = __shfl_up_sync(0xffffffffu, ws, d);
                    if (lane >= d) ws += t2;
                }
                wsum[lane] = ws;
            }
            __syncthreads();
            int warp_excl = (wid == 0) ? 0 : wsum[wid - 1];
            int excl = s - v + warp_excl + carry_s;
            if (i < NN) { g_off[i] = excl; g_cur[i] = excl; }
            int total = wsum[31];
            __syncthreads();
            if (tid == 0) carry_s += total;
            __syncthreads();
        }
        if (tid == 0) g_off[NN] = carry_s;
        return;
    }

    if (blk == 19) {
        if (tid == 0) {
            float m = -1e30f;
            for (int t = 0; t < TT; t++) m = fmaxf(m, att[t]);
            float e[TT], s = 0.0f;
            for (int t = 0; t < TT; t++) { e[t] = __expf(att[t] - m); s += e[t]; }
            float inv = 0.5f / s;                      // fold the 1/2 here
            for (int t = 0; t < TT; t++) g_p[t] = e[t] * inv;
        }
        return;
    }

    if (tid >= UU) return;
    int u = tid;
    bool isz = blk <= 9;
    int f = isz ? blk - 1 : blk - 10;
    const float* W  = isz ? Wz : Wh;
    const float* L  = isz ? Lzw : Lhw;
    const float* b  = isz ? bz : bh;
    const float* Lb = isz ? Lzb : Lhb;
    float* M = isz ? g_Mz : g_Mh;
    float* c = isz ? g_cz : g_ch;
    float scale = isz ? 0.5f : 1.0f;                   // tanh(az/2) prescale

    __shared__ float srow[UU];
    if (f < FF) {
        srow[u] = W[f * UU + u];
        __syncthreads();
        float s = 0.0f;
        for (int k = 0; k < UU; k++) s = fmaf(srow[k], L[k * UU + u], s);
        M[f * UU + u] = scale * s;
    } else {
        srow[u] = b[u];
        __syncthreads();
        float s = Lb[u];
        for (int k = 0; k < UU; k++) s = fmaf(srow[k], L[k * UU + u], s);
        c[u] = scale * s;
    }
}

// ---------------- phase 3: fill per-dst edge slots (4 edges/thread) ----------------
__global__ void k_fill(const int* __restrict__ ei, const float* __restrict__ w) {
    int t = blockIdx.x * blockDim.x + threadIdx.x;
    if (t >= EQ) return;
    int   src[4], dst[4];
    float wv[4];
#pragma unroll
    for (int j = 0; j < 4; j++) {
        int e = t + j * EQ;
        src[j] = __ldg(ei + e);
        dst[j] = __ldg(ei + EE + e);
        wv[j]  = __ldg(w + e);
    }
    float ds[4], dd[4];
#pragma unroll
    for (int j = 0; j < 4; j++) {
        ds[j] = __uint_as_float(g_dc[src[j]]) + 1.0f;
        dd[j] = __uint_as_float(g_dc[dst[j]]) + 1.0f;
    }
#pragma unroll
    for (int j = 0; j < 4; j++) {
        float nrm = rsqrtf(ds[j]) * wv[j] * rsqrtf(dd[j]);
        int p = atomicAdd(&g_cur[dst[j]], 1);
        g_edge[p] = make_uint2((unsigned)src[j], __float_as_uint(nrm));
    }
}

// ---------------- phase 4: fused gather + gates + epilogue ----------------
#define NPB 8
__global__ void __launch_bounds__(UU) k_dense(const float4* __restrict__ x4,
                                              const float* __restrict__ lin_w,
                                              const float* __restrict__ lin_b,
                                              float* __restrict__ out) {
    __shared__ __align__(16) float sY[NPB][FT];
    __shared__ float sH[NPB][UU];
    __shared__ float sp[TT];

    int u = threadIdx.x;
    int lane = u & 31;
    int wid = u >> 5;
    int n0 = blockIdx.x * NPB;

    // ---- gather: warp w aggregates node n0+w into sY[w], MLP=4 ----
    {
        int node = n0 + wid;
        int beg = g_off[node], end = g_off[node + 1];
        int ln = (lane < FT4) ? lane : 0;             // clamp: lanes 24-31 duplicate lane0
        float s = 1.0f / (__uint_as_float(g_dc[node]) + 1.0f);   // dinv^2 (self-loop)
        float4 a0 = __ldg(x4 + (size_t)node * FT4 + ln);
        a0.x *= s; a0.y *= s; a0.z *= s; a0.w *= s;
        float4 a1 = make_float4(0.f, 0.f, 0.f, 0.f);
        float4 a2 = make_float4(0.f, 0.f, 0.f, 0.f);
        float4 a3 = make_float4(0.f, 0.f, 0.f, 0.f);

        int i = beg;
        for (; i + 4 <= end; i += 4) {
            uint2 e0 = __ldg(&g_edge[i + 0]);
            uint2 e1 = __ldg(&g_edge[i + 1]);
            uint2 e2 = __ldg(&g_edge[i + 2]);
            uint2 e3 = __ldg(&g_edge[i + 3]);
            float4 v0 = __ldg(x4 + (size_t)e0.x * FT4 + ln);
            float4 v1 = __ldg(x4 + (size_t)e1.x * FT4 + ln);
            float4 v2 = __ldg(x4 + (size_t)e2.x * FT4 + ln);
            float4 v3 = __ldg(x4 + (size_t)e3.x * FT4 + ln);
            a0 = fma4s(__uint_as_float(e0.y), v0, a0);
            a1 = fma4s(__uint_as_float(e1.y), v1, a1);
            a2 = fma4s(__uint_as_float(e2.y), v2, a2);
            a3 = fma4s(__uint_as_float(e3.y), v3, a3);
        }
        for (; i < end; i++) {
            uint2 e = __ldg(&g_edge[i]);
            float4 v = __ldg(x4 + (size_t)e.x * FT4 + ln);
            a0 = fma4s(__uint_as_float(e.y), v, a0);
        }
        a0.x += a1.x + a2.x + a3.x;
        a0.y += a1.y + a2.y + a3.y;
        a0.z += a1.z + a2.z + a3.z;
        a0.w += a1.w + a2.w + a3.w;
        if (lane < FT4)
            reinterpret_cast<float4*>(sY[wid])[lane] = a0;
    }
    if (u < TT) sp[u] = g_p[u];                    // already 0.5*p
    __syncthreads();

    // ---- gates: thread u, loop nodes ----
    unsigned long long mz2[FF], mh2[FF];
#pragma unroll
    for (int f = 0; f < FF; f++) {
        float mz = g_Mz[f * UU + u];
        float mh = g_Mh[f * UU + u];
        mz2[f] = pack2(mz, mz);
        mh2[f] = pack2(mh, mh);
    }
    unsigned long long cz2, ch2;
    { float cz = g_cz[u], ch = g_ch[u]; cz2 = pack2(cz, cz); ch2 = pack2(ch, ch); }

#pragma unroll
    for (int nn = 0; nn < NPB; nn++) {
        const unsigned long long* yrow = reinterpret_cast<const unsigned long long*>(sY[nn]);
        float acc = 0.0f;
#pragma unroll
        for (int tp = 0; tp < TT / 2; tp++) {
            unsigned long long az = cz2, ah = ch2;
#pragma unroll
            for (int f = 0; f < FF; f++) {
                unsigned long long y2 = yrow[f * (TT / 2) + tp];
                az = fma2(y2, mz2[f], az);          // az holds a/2 (prescaled)
                ah = fma2(y2, mh2[f], ah);
            }
            float a0, a1, h0, h1;
            unpack2(az, a0, a1);
            unpack2(ah, h0, h1);
            float tz0 = tanh_a(a0), tz1 = tanh_a(a1);
            float q0 = sp[2 * tp], q1 = sp[2 * tp + 1];
            float r0 = fmaf(-tz0, q0, q0);          // q*(1-tanh(a/2)) = p*(1-sigmoid)
            float r1 = fmaf(-tz1, q1, q1);
            acc = fmaf(r0, tanh_a(h0), acc);
            acc = fmaf(r1, tanh_a(h1), acc);
        }
        sH[nn][u] = fmaxf(acc, 0.0f);
    }
    __syncthreads();

    // ---- epilogue: warp w -> node n0+w ----
    {
        float part[TT];
#pragma unroll
        for (int t = 0; t < TT; t++) part[t] = 0.0f;
#pragma unroll
        for (int q = 0; q < 8; q++) {
            int k = lane + 32 * q;                  // conflict-free (lane-major)
            float h = sH[wid][k];
            const float4* wr = reinterpret_cast<const float4*>(lin_w + k * TT);
            float4 w0 = __ldg(wr + 0);
            float4 w1 = __ldg(wr + 1);
            float4 w2 = __ldg(wr + 2);
            part[0] = fmaf(h, w0.x, part[0]);  part[1]  = fmaf(h, w0.y, part[1]);
            part[2] = fmaf(h, w0.z, part[2]);  part[3]  = fmaf(h, w0.w, part[3]);
            part[4] = fmaf(h, w1.x, part[4]);  part[5]  = fmaf(h, w1.y, part[5]);
            part[6] = fmaf(h, w1.z, part[6]);  part[7]  = fmaf(h, w1.w, part[7]);
            part[8] = fmaf(h, w2.x, part[8]);  part[9]  = fmaf(h, w2.y, part[9]);
            part[10] = fmaf(h, w2.z, part[10]); part[11] = fmaf(h, w2.w, part[11]);
        }
#pragma unroll
        for (int d = 16; d > 0; d >>= 1)
#pragma unroll
            for (int t = 0; t < TT; t++)
                part[t] += __shfl_xor_sync(0xffffffffu, part[t], d);
        if (lane < TT)
            out[(size_t)(n0 + wid) * TT + lane] = part[lane] + __ldg(lin_b + lane);
    }
}

// ---------------- launcher ----------------
extern "C" void kernel_launch(void* const* d_in, const int* in_sizes, int n_in,
                              void* d_out, int out_size) {
    const float* x      = (const float*)d_in[0];
    const int*   ei     = (const int*)d_in[1];
    const float* ew     = (const float*)d_in[2];
    const float* att    = (const float*)d_in[3];
    const float* Wz     = (const float*)d_in[4];
    const float* bz     = (const float*)d_in[5];
    // d_in[6..7] (Wr, br) dead: r-gate multiplies H0 == 0
    const float* Wh     = (const float*)d_in[8];
    const float* bh     = (const float*)d_in[9];
    const float* Lzw    = (const float*)d_in[10];
    const float* Lzb    = (const float*)d_in[11];
    // d_in[12..13] (Lrw, Lrb) dead
    const float* Lhw    = (const float*)d_in[14];
    const float* Lhb    = (const float*)d_in[15];
    const float* lin_w  = (const float*)d_in[16];
    const float* lin_b  = (const float*)d_in[17];
    float* out = (float*)d_out;

    void* dc_ptr = nullptr;
    cudaGetSymbolAddress(&dc_ptr, g_dc);

    cudaMemsetAsync(dc_ptr, 0, 2 * NN * sizeof(unsigned));
    k_edges<<<(EQ + 255) / 256, 256>>>(ei, ew);
    k_scanprep<<<20, 1024>>>(Wz, Lzw, bz, Lzb, Wh, Lhw, bh, Lhb, att);
    k_fill<<<(EQ + 255) / 256, 256>>>(ei, ew);
    k_dense<<<NN / NPB, UU>>>((const float4*)x, lin_w, lin_b, out);
}

// round 6
// speedup vs baseline: 1.6878x; 1.0010x over previous
#include <cuda_runtime.h>
#include <cstdint>

#define NN 20000
#define EE 320000
#define FF 8
#define TT 12
#define UU 256
#define FT 96   // FF*TT
#define FT4 24  // FT/4
#define EQ (EE / 4)   // edges per thread-quarter

// ---------------- device scratch ----------------
// g_dc: [0,NN) = deg-minus-selfloop (float bits), [NN,2NN) = cnt (int). Zero-init by memset.
__device__ unsigned g_dc[2 * NN];
__device__ int   g_off[NN + 1];
__device__ int   g_cur[NN];
__device__ uint2 g_edge[EE];        // (src, norm-bits) per dst-sorted slot
__device__ float g_Mz[FF * UU];     // prescaled by 0.5
__device__ float g_Mh[FF * UU];
__device__ float g_cz[UU];          // prescaled by 0.5
__device__ float g_ch[UU];
__device__ float g_p[TT];           // 0.5 * softmax(attention)

// ---------------- fast math ----------------
__device__ __forceinline__ float tanh_a(float x) {
    float y; asm("tanh.approx.f32 %0, %1;" : "=f"(y) : "f"(x)); return y;
}
__device__ __forceinline__ unsigned long long fma2(unsigned long long a,
                                                   unsigned long long b,
                                                   unsigned long long c) {
    unsigned long long d;
    asm("fma.rn.f32x2 %0, %1, %2, %3;" : "=l"(d) : "l"(a), "l"(b), "l"(c));
    return d;
}
__device__ __forceinline__ unsigned long long pack2(float lo, float hi) {
    unsigned long long r;
    asm("mov.b64 %0, {%1,%2};" : "=l"(r) : "f"(lo), "f"(hi));
    return r;
}
__device__ __forceinline__ void unpack2(unsigned long long v, float& lo, float& hi) {
    asm("mov.b64 {%0,%1}, %2;" : "=f"(lo), "=f"(hi) : "l"(v));
}
__device__ __forceinline__ float4 fma4s(float s, float4 v, float4 a) {
    a.x = fmaf(s, v.x, a.x); a.y = fmaf(s, v.y, a.y);
    a.z = fmaf(s, v.z, a.z); a.w = fmaf(s, v.w, a.w);
    return a;
}

// ---------------- phase 1: per-dst degree + edge counts (4 edges/thread) ----------------
__global__ void k_edges(const int* __restrict__ ei, const float* __restrict__ w) {
    int t = blockIdx.x * blockDim.x + threadIdx.x;
    if (t >= EQ) return;
    int   dst[4];
    float wv[4];
#pragma unroll
    for (int j = 0; j < 4; j++) {
        int e = t + j * EQ;
        dst[j] = __ldg(ei + EE + e);
        wv[j]  = __ldg(w + e);
    }
#pragma unroll
    for (int j = 0; j < 4; j++) {
        atomicAdd(reinterpret_cast<float*>(&g_dc[dst[j]]), wv[j]);
        atomicAdd(reinterpret_cast<int*>(&g_dc[NN + dst[j]]), 1);
    }
}

// ---------------- phase 2: scan (blk 0) + weight-fold (1..18) + softmax (19) ----------------
#define CHUNKS ((NN + 1023) / 1024)
__global__ void __launch_bounds__(1024) k_scanprep(
        const float* __restrict__ Wz, const float* __restrict__ Lzw,
        const float* __restrict__ bz, const float* __restrict__ Lzb,
        const float* __restrict__ Wh, const float* __restrict__ Lhw,
        const float* __restrict__ bh, const float* __restrict__ Lhb,
        const float* __restrict__ att) {
    int blk = blockIdx.x;
    int tid = threadIdx.x;

    if (blk == 0) {
        __shared__ int wsum[32];
        __shared__ int carry_s;
        int lane = tid & 31, wid = tid >> 5;
        int vv[CHUNKS];
#pragma unroll
        for (int c = 0; c < CHUNKS; c++) {           // front-batch all loads (MLP=20)
            int i = c * 1024 + tid;
            vv[c] = (i < NN) ? (int)g_dc[NN + i] : 0;
        }
        if (tid == 0) carry_s = 0;
        __syncthreads();
#pragma unroll
        for (int c = 0; c < CHUNKS; c++) {
            int i = c * 1024 + tid;
            int v = vv[c];
            int s = v;
#pragma unroll
            for (int d = 1; d < 32; d <<= 1) {
                int t2 = __shfl_up_sync(0xffffffffu, s, d);
                if (lane >= d) s += t2;
            }
            if (lane == 31) wsum[wid] = s;
            __syncthreads();
            if (wid == 0) {
                int ws = wsum[lane];
#pragma unroll
                for (int d = 1; d < 32; d <<= 1) {
                    int t2 = __shfl_up_sync(0xffffffffu, ws, d);
                    if (lane >= d) ws += t2;
                }
                wsum[lane] = ws;
            }
            __syncthreads();
            int warp_excl = (wid == 0) ? 0 : wsum[wid - 1];
            int excl = s - v + warp_excl + carry_s;
            if (i < NN) { g_off[i] = excl; g_cur[i] = excl; }
            int total = wsum[31];
            __syncthreads();
            if (tid == 0) carry_s += total;
            __syncthreads();
        }
        if (tid == 0) g_off[NN] = carry_s;
        return;
    }

    if (blk == 19) {
        if (tid == 0) {
            float m = -1e30f;
            for (int t = 0; t < TT; t++) m = fmaxf(m, att[t]);
            float e[TT], s = 0.0f;
            for (int t = 0; t < TT; t++) { e[t] = __expf(att[t] - m); s += e[t]; }
            float inv = 0.5f / s;                      // fold the 1/2 here
            for (int t = 0; t < TT; t++) g_p[t] = e[t] * inv;
        }
        return;
    }

    if (tid >= UU) return;
    int u = tid;
    bool isz = blk <= 9;
    int f = isz ? blk - 1 : blk - 10;
    const float* W  = isz ? Wz : Wh;
    const float* L  = isz ? Lzw : Lhw;
    const float* b  = isz ? bz : bh;
    const float* Lb = isz ? Lzb : Lhb;
    float* M = isz ? g_Mz : g_Mh;
    float* c = isz ? g_cz : g_ch;
    float scale = isz ? 0.5f : 1.0f;                   // tanh(az/2) prescale

    __shared__ float srow[UU];
    if (f < FF) {
        srow[u] = W[f * UU + u];
        __syncthreads();
        float s = 0.0f;
        for (int k = 0; k < UU; k++) s = fmaf(srow[k], L[k * UU + u], s);
        M[f * UU + u] = scale * s;
    } else {
        srow[u] = b[u];
        __syncthreads();
        float s = Lb[u];
        for (int k = 0; k < UU; k++) s = fmaf(srow[k], L[k * UU + u], s);
        c[u] = scale * s;
    }
}

// ---------------- phase 3: fill per-dst edge slots (4 edges/thread) ----------------
__global__ void k_fill(const int* __restrict__ ei, const float* __restrict__ w) {
    int t = blockIdx.x * blockDim.x + threadIdx.x;
    if (t >= EQ) return;
    int   src[4], dst[4];
    float wv[4];
#pragma unroll
    for (int j = 0; j < 4; j++) {
        int e = t + j * EQ;
        src[j] = __ldg(ei + e);
        dst[j] = __ldg(ei + EE + e);
        wv[j]  = __ldg(w + e);
    }
    float ds[4], dd[4];
#pragma unroll
    for (int j = 0; j < 4; j++) {
        ds[j] = __uint_as_float(g_dc[src[j]]) + 1.0f;
        dd[j] = __uint_as_float(g_dc[dst[j]]) + 1.0f;
    }
#pragma unroll
    for (int j = 0; j < 4; j++) {
        float nrm = rsqrtf(ds[j]) * wv[j] * rsqrtf(dd[j]);
        int p = atomicAdd(&g_cur[dst[j]], 1);
        g_edge[p] = make_uint2((unsigned)src[j], __float_as_uint(nrm));
    }
}

// ---------------- phase 4: fused gather + gates + epilogue ----------------
#define NPB 8
__global__ void __launch_bounds__(UU, 4) k_dense(const float4* __restrict__ x4,
                                                 const float* __restrict__ lin_w,
                                                 const float* __restrict__ lin_b,
                                                 float* __restrict__ out) {
    __shared__ __align__(16) float sY[NPB][FT];
    __shared__ float sH[NPB][UU];
    __shared__ float sp[TT];

    int u = threadIdx.x;
    int lane = u & 31;
    int wid = u >> 5;
    int n0 = blockIdx.x * NPB;

    // ---- gather: warp w aggregates node n0+w into sY[w], MLP=2 (reg-lean) ----
    {
        int node = n0 + wid;
        int beg = g_off[node], end = g_off[node + 1];
        int ln = (lane < FT4) ? lane : 0;             // clamp: lanes 24-31 duplicate lane0
        float s = 1.0f / (__uint_as_float(g_dc[node]) + 1.0f);   // dinv^2 (self-loop)
        float4 a0 = __ldg(x4 + (size_t)node * FT4 + ln);
        a0.x *= s; a0.y *= s; a0.z *= s; a0.w *= s;
        float4 a1 = make_float4(0.f, 0.f, 0.f, 0.f);

        int i = beg;
        for (; i + 2 <= end; i += 2) {
            uint2 e0 = __ldg(&g_edge[i + 0]);
            uint2 e1 = __ldg(&g_edge[i + 1]);
            float4 v0 = __ldg(x4 + (size_t)e0.x * FT4 + ln);
            float4 v1 = __ldg(x4 + (size_t)e1.x * FT4 + ln);
            a0 = fma4s(__uint_as_float(e0.y), v0, a0);
            a1 = fma4s(__uint_as_float(e1.y), v1, a1);
        }
        if (i < end) {
            uint2 e = __ldg(&g_edge[i]);
            float4 v = __ldg(x4 + (size_t)e.x * FT4 + ln);
            a0 = fma4s(__uint_as_float(e.y), v, a0);
        }
        a0.x += a1.x; a0.y += a1.y; a0.z += a1.z; a0.w += a1.w;
        if (lane < FT4)
            reinterpret_cast<float4*>(sY[wid])[lane] = a0;
    }
    if (u < TT) sp[u] = g_p[u];                    // already 0.5*p
    __syncthreads();

    // ---- gates: thread u, loop nodes ----
    unsigned long long mz2[FF], mh2[FF];
#pragma unroll
    for (int f = 0; f < FF; f++) {
        float mz = g_Mz[f * UU + u];
        float mh = g_Mh[f * UU + u];
        mz2[f] = pack2(mz, mz);
        mh2[f] = pack2(mh, mh);
    }
    unsigned long long cz2, ch2;
    { float cz = g_cz[u], ch = g_ch[u]; cz2 = pack2(cz, cz); ch2 = pack2(ch, ch); }

#pragma unroll
    for (int nn = 0; nn < NPB; nn++) {
        const unsigned long long* yrow = reinterpret_cast<const unsigned long long*>(sY[nn]);
        float acc = 0.0f;
#pragma unroll
        for (int tp = 0; tp < TT / 2; tp++) {
            unsigned long long az = cz2, ah = ch2;
#pragma unroll
            for (int f = 0; f < FF; f++) {
                unsigned long long y2 = yrow[f * (TT / 2) + tp];
                az = fma2(y2, mz2[f], az);          // az holds a/2 (prescaled)
                ah = fma2(y2, mh2[f], ah);
            }
            float a0, a1, h0, h1;
            unpack2(az, a0, a1);
            unpack2(ah, h0, h1);
            float tz0 = tanh_a(a0), tz1 = tanh_a(a1);
            float q0 = sp[2 * tp], q1 = sp[2 * tp + 1];
            float r0 = fmaf(-tz0, q0, q0);          // q*(1-tanh(a/2)) = p*(1-sigmoid)
            float r1 = fmaf(-tz1, q1, q1);
            acc = fmaf(r0, tanh_a(h0), acc);
            acc = fmaf(r1, tanh_a(h1), acc);
        }
        sH[nn][u] = fmaxf(acc, 0.0f);
    }
    __syncthreads();

    // ---- epilogue: warp w -> node n0+w ----
    {
        float part[TT];
#pragma unroll
        for (int t = 0; t < TT; t++) part[t] = 0.0f;
#pragma unroll
        for (int q = 0; q < 8; q++) {
            int k = lane + 32 * q;                  // conflict-free (lane-major)
            float h = sH[wid][k];
            const float4* wr = reinterpret_cast<const float4*>(lin_w + k * TT);
            float4 w0 = __ldg(wr + 0);
            float4 w1 = __ldg(wr + 1);
            float4 w2 = __ldg(wr + 2);
            part[0] = fmaf(h, w0.x, part[0]);  part[1]  = fmaf(h, w0.y, part[1]);
            part[2] = fmaf(h, w0.z, part[2]);  part[3]  = fmaf(h, w0.w, part[3]);
            part[4] = fmaf(h, w1.x, part[4]);  part[5]  = fmaf(h, w1.y, part[5]);
            part[6] = fmaf(h, w1.z, part[6]);  part[7]  = fmaf(h, w1.w, part[7]);
            part[8] = fmaf(h, w2.x, part[8]);  part[9]  = fmaf(h, w2.y, part[9]);
            part[10] = fmaf(h, w2.z, part[10]); part[11] = fmaf(h, w2.w, part[11]);
        }
#pragma unroll
        for (int d = 16; d > 0; d >>= 1)
#pragma unroll
            for (int t = 0; t < TT; t++)
                part[t] += __shfl_xor_sync(0xffffffffu, part[t], d);
        if (lane < TT)
            out[(size_t)(n0 + wid) * TT + lane] = part[lane] + __ldg(lin_b + lane);
    }
}

// ---------------- launcher ----------------
extern "C" void kernel_launch(void* const* d_in, const int* in_sizes, int n_in,
                              void* d_out, int out_size) {
    const float* x      = (const float*)d_in[0];
    const int*   ei     = (const int*)d_in[1];
    const float* ew     = (const float*)d_in[2];
    const float* att    = (const float*)d_in[3];
    const float* Wz     = (const float*)d_in[4];
    const float* bz     = (const float*)d_in[5];
    // d_in[6..7] (Wr, br) dead: r-gate multiplies H0 == 0
    const float* Wh     = (const float*)d_in[8];
    const float* bh     = (const float*)d_in[9];
    const float* Lzw    = (const float*)d_in[10];
    const float* Lzb    = (const float*)d_in[11];
    // d_in[12..13] (Lrw, Lrb) dead
    const float* Lhw    = (const float*)d_in[14];
    const float* Lhb    = (const float*)d_in[15];
    const float* lin_w  = (const float*)d_in[16];
    const float* lin_b  = (const float*)d_in[17];
    float* out = (float*)d_out;

    void* dc_ptr = nullptr;
    cudaGetSymbolAddress(&dc_ptr, g_dc);

    cudaMemsetAsync(dc_ptr, 0, 2 * NN * sizeof(unsigned));
    k_edges<<<(EQ + 255) / 256, 256>>>(ei, ew);
    k_scanprep<<<20, 1024>>>(Wz, Lzw, bz, Lzb, Wh, Lhw, bh, Lhb, att);
    k_fill<<<(EQ + 255) / 256, 256>>>(ei, ew);
    k_dense<<<NN / NPB, UU>>>((const float4*)x, lin_w, lin_b, out);
}